// round 10
// baseline (speedup 1.0000x reference)
#include <cuda_runtime.h>
#include <cuda_bf16.h>
#include <cstdint>

using bf16 = __nv_bfloat16;

// Problem dims
static constexpr int NB = 8, NS = 1024, ND = 512, NK = 64, NH = 8;

static constexpr size_t SZ_X  = (size_t)NB * NS * ND;          // 4,194,304

// fp8 scale factors
#define SC_P  256.0f
#define SC_O  32.0f
#define SC_WO 64.0f

// -------- static scratch (no runtime allocation allowed) --------
__device__ bf16     g_xb [SZ_X];
__device__ bf16     g_qb [SZ_X];
__device__ bf16     g_kb [SZ_X];
__device__ bf16     g_wqt[ND * (NK * NH)];        // [512][512]  WqT bf16
__device__ bf16     g_wkt[ND * (NK * NH)];        // [512][512]  WkT bf16
__device__ bf16     g_wvt[(ND * NH) * ND];        // [4096][512] WvT bf16
__device__ uint16_t g_wot8[ND * (ND * NH / 2)];   // [512][2048u] WoT fp8 pairs (x64)
__device__ uint16_t g_vt8[(size_t)NB * (ND * NH) * (NS / 2)];  // [b][4096][512u] V^T fp8
__device__ uint16_t g_ob8[(size_t)NB * NS * (NH * ND / 2)];    // [8192][2048u] O fp8 (x32)
__device__ float    g_y  [SZ_X];                  // pre-LN (o@Wo + bo + x)

// ---------------------------------------------------------------
__device__ __forceinline__ uint32_t pack_bf16(float lo, float hi) {
    return ((uint32_t)__bfloat16_as_ushort(__float2bfloat16(hi)) << 16) |
            (uint32_t)__bfloat16_as_ushort(__float2bfloat16(lo));
}

__device__ __forceinline__ uint16_t pack_e4m3(float lo, float hi) {
    uint16_t r;
    asm("cvt.rn.satfinite.e4m3x2.f32 %0, %1, %2;" : "=h"(r) : "f"(hi), "f"(lo));
    return r;
}

__device__ __forceinline__ void mma16816(float* d, const uint32_t* a, const uint32_t* b) {
    asm volatile(
        "mma.sync.aligned.m16n8k16.row.col.f32.bf16.bf16.f32 "
        "{%0,%1,%2,%3}, {%4,%5,%6,%7}, {%8,%9}, {%0,%1,%2,%3};\n"
        : "+f"(d[0]), "+f"(d[1]), "+f"(d[2]), "+f"(d[3])
        : "r"(a[0]), "r"(a[1]), "r"(a[2]), "r"(a[3]), "r"(b[0]), "r"(b[1]));
}

__device__ __forceinline__ void mma16832(float* d, const uint32_t* a, const uint32_t* b) {
    asm volatile(
        "mma.sync.aligned.m16n8k32.row.col.f32.e4m3.e4m3.f32 "
        "{%0,%1,%2,%3}, {%4,%5,%6,%7}, {%8,%9}, {%0,%1,%2,%3};\n"
        : "+f"(d[0]), "+f"(d[1]), "+f"(d[2]), "+f"(d[3])
        : "r"(a[0]), "r"(a[1]), "r"(a[2]), "r"(a[3]), "r"(b[0]), "r"(b[1]));
}

// ldmatrix x4: loads 4 8x8 b16-unit matrices; per-lane row address in shared.
__device__ __forceinline__ void ldsm_x4(uint32_t& r0, uint32_t& r1, uint32_t& r2, uint32_t& r3,
                                        const void* p) {
    uint32_t a = (uint32_t)__cvta_generic_to_shared(p);
    asm volatile("ldmatrix.sync.aligned.m8n8.x4.shared.b16 {%0,%1,%2,%3}, [%4];"
                 : "=r"(r0), "=r"(r1), "=r"(r2), "=r"(r3) : "r"(a));
}

__device__ __forceinline__ void cpasync16(void* s, const void* g) {
    uint32_t sa = (uint32_t)__cvta_generic_to_shared(s);
    asm volatile("cp.async.cg.shared.global [%0], [%1], 16;\n" :: "r"(sa), "l"(g));
}
__device__ __forceinline__ void cpcommit() { asm volatile("cp.async.commit_group;\n" ::: "memory"); }
__device__ __forceinline__ void cpwait0()  { asm volatile("cp.async.wait_group 0;\n" ::: "memory"); }
__device__ __forceinline__ void cpwait1()  { asm volatile("cp.async.wait_group 1;\n" ::: "memory"); }

// -------- elementwise convert fp32 -> bf16 --------
__global__ void f32_to_bf16_k(const float* __restrict__ in, bf16* __restrict__ out, int n) {
    int i = (blockIdx.x * blockDim.x + threadIdx.x) * 4;
    if (i >= n) return;
    float4 v = *reinterpret_cast<const float4*>(in + i);
    uint2 u;
    u.x = pack_bf16(v.x, v.y);
    u.y = pack_bf16(v.z, v.w);
    *reinterpret_cast<uint2*>(out + i) = u;
}

// -------- transpose + convert: out[c][r] = in[r][c] (bf16) --------
__global__ void transpose_to_bf16(const float* __restrict__ in, bf16* __restrict__ out,
                                  int R, int C) {
    __shared__ float t[32][33];
    int c0 = blockIdx.x * 32, r0 = blockIdx.y * 32;
    int tx = threadIdx.x;
    for (int i = threadIdx.y; i < 32; i += 8)
        t[i][tx] = in[(size_t)(r0 + i) * C + c0 + tx];
    __syncthreads();
    for (int i = threadIdx.y; i < 32; i += 8)
        out[(size_t)(c0 + i) * R + r0 + tx] = __float2bfloat16(t[tx][i]);
}

// -------- transpose + convert to fp8 pairs: out_u16[c][r/2] = pack(in[r][c], in[r+1][c]) * scale
__global__ void transpose_to_fp8(const float* __restrict__ in, uint16_t* __restrict__ out,
                                 int R, int C, float scale) {
    __shared__ float t[32][33];
    int c0 = blockIdx.x * 32, r0 = blockIdx.y * 32;
    int tx = threadIdx.x;
    for (int i = threadIdx.y; i < 32; i += 8)
        t[i][tx] = in[(size_t)(r0 + i) * C + c0 + tx];
    __syncthreads();
    if (tx < 16)
        for (int i = threadIdx.y; i < 32; i += 8)
            out[(size_t)(c0 + i) * (R / 2) + r0 / 2 + tx] =
                pack_e4m3(t[2 * tx][i] * scale, t[2 * tx + 1][i] * scale);
}

// -------- generic batched GEMM (cp.async double-buffered, ldmatrix frags) --------
// Element unit = 16 bits (bf16, or a pair of fp8 when FP8=1).
// C[m,n] = alpha * sum_k A[m,k] * B[n,k]
// MODE 1: bf16 store   MODE 2: fp32 store + bias[n] + resid[m,n]   MODE 3: fp8-pair store
// K quantities (Kd, lda, ldb) are in 16-bit units. ldc: MODE3 in units, else elements.
#define BM 128
#define BN 128
#define BK 32
#define BKP 40   // padded smem row (units); 80B row stride -> ldmatrix conflict-free

template <int MODE, int FP8>
__global__ __launch_bounds__(256, 2)
void gemm_tn(const bf16* __restrict__ A, const bf16* __restrict__ B,
             void* __restrict__ Cv,
             int M, int N, int Kd, int lda, int ldb, int ldc,
             long long sA1, long long sA2, long long sB1, long long sB2,
             long long sC1, long long sC2, int Z1,
             float alpha, const float* __restrict__ bias,
             const float* __restrict__ resid, int ldres) {
    int z = blockIdx.z;
    int z1 = z % Z1, z2 = z / Z1;
    A += (size_t)z1 * sA1 + (size_t)z2 * sA2;
    B += (size_t)z1 * sB1 + (size_t)z2 * sB2;
    long long coff = (long long)z1 * sC1 + (long long)z2 * sC2;

    __shared__ alignas(16) bf16 As[2][BM][BKP];
    __shared__ alignas(16) bf16 Bs[2][BN][BKP];

    int tid  = threadIdx.x;
    int warp = tid >> 5, lane = tid & 31;
    int wm = (warp & 1) * 64;
    int wn = (warp >> 1) * 32;
    int bm0 = blockIdx.y * BM;
    int bn0 = blockIdx.x * BN;

    float acc[4][4][4];
#pragma unroll
    for (int i = 0; i < 4; i++)
#pragma unroll
        for (int j = 0; j < 4; j++)
#pragma unroll
            for (int r = 0; r < 4; r++) acc[i][j][r] = 0.f;

    int lr = tid >> 2;
    int lc = (tid & 3) * 8;
    int rq = lane >> 2;
    int cq = lane & 3;
    int l16 = lane & 15, lhi = (lane >> 4) * 8;

#pragma unroll
    for (int i = 0; i < 2; i++) {
        int r = lr + i * 64;
        cpasync16(&As[0][r][lc], A + (size_t)(bm0 + r) * lda + lc);
        cpasync16(&Bs[0][r][lc], B + (size_t)(bn0 + r) * ldb + lc);
    }
    cpcommit();

    int p = 0;
    for (int kt = 0; kt < Kd; kt += BK, p ^= 1) {
        cpwait0();
        __syncthreads();
        if (kt + BK < Kd) {
            int np = p ^ 1;
#pragma unroll
            for (int i = 0; i < 2; i++) {
                int r = lr + i * 64;
                cpasync16(&As[np][r][lc], A + (size_t)(bm0 + r) * lda + kt + BK + lc);
                cpasync16(&Bs[np][r][lc], B + (size_t)(bn0 + r) * ldb + kt + BK + lc);
            }
            cpcommit();
        }

#pragma unroll
        for (int ks = 0; ks < 2; ks++) {
            int kk = ks * 16 + lhi;
            uint32_t afr[4][4];
#pragma unroll
            for (int i = 0; i < 4; i++)
                ldsm_x4(afr[i][0], afr[i][1], afr[i][2], afr[i][3],
                        &As[p][wm + i * 16 + l16][kk]);
            uint32_t bfr[4][2];
#pragma unroll
            for (int jp = 0; jp < 2; jp++) {
                uint32_t b0, b1, b2, b3;
                ldsm_x4(b0, b1, b2, b3, &Bs[p][wn + jp * 16 + l16][kk]);
                bfr[2 * jp][0] = b0; bfr[2 * jp][1] = b2;
                bfr[2 * jp + 1][0] = b1; bfr[2 * jp + 1][1] = b3;
            }
#pragma unroll
            for (int i = 0; i < 4; i++)
#pragma unroll
                for (int j = 0; j < 4; j++) {
                    if (FP8) mma16832(acc[i][j], afr[i], bfr[j]);
                    else     mma16816(acc[i][j], afr[i], bfr[j]);
                }
        }
        __syncthreads();
    }

    int cq2 = cq * 2;
#pragma unroll
    for (int i = 0; i < 4; i++) {
#pragma unroll
        for (int j = 0; j < 4; j++) {
            int row = bm0 + wm + i * 16 + rq;
            int col = bn0 + wn + j * 8 + cq2;
            float c0 = acc[i][j][0] * alpha, c1 = acc[i][j][1] * alpha;
            float c2 = acc[i][j][2] * alpha, c3 = acc[i][j][3] * alpha;
            if (MODE == 2) {
                float* Cf = (float*)Cv + coff;
                float b0v = bias[col], b1v = bias[col + 1];
                const float* r0p = resid + (size_t)row * ldres + col;
                const float* r1p = resid + (size_t)(row + 8) * ldres + col;
                c0 += b0v + r0p[0]; c1 += b1v + r0p[1];
                c2 += b0v + r1p[0]; c3 += b1v + r1p[1];
                *reinterpret_cast<float2*>(Cf + (size_t)row * ldc + col)       = make_float2(c0, c1);
                *reinterpret_cast<float2*>(Cf + (size_t)(row + 8) * ldc + col) = make_float2(c2, c3);
            } else if (MODE == 1) {
                bf16* Cb = (bf16*)Cv + coff;
                *reinterpret_cast<uint32_t*>(Cb + (size_t)row * ldc + col)       = pack_bf16(c0, c1);
                *reinterpret_cast<uint32_t*>(Cb + (size_t)(row + 8) * ldc + col) = pack_bf16(c2, c3);
            } else {  // MODE 3: fp8 pair store, ldc in units
                uint16_t* C8 = (uint16_t*)Cv + coff;
                C8[(size_t)row * ldc + (col >> 1)]       = pack_e4m3(c0, c1);
                C8[(size_t)(row + 8) * ldc + (col >> 1)] = pack_e4m3(c2, c3);
            }
        }
    }
}

// ================================================================
// Fused flash attention: bf16 QK^T scores + fp32 softmax; P and V
// in fp8 (e4m3) for the P·V mma (m16n8k32, 2x rate). P routed
// through a per-warp smem tile (stride 144B, conflict-free ldmatrix).
// d-chunk = 256; q-tile 128; 8 s-iters of 128. grid = (16, 64).
// Smem: Q[128*72] | K[2][128*72] | V8[2][256*72u] | P8[8][16*72u]  (~144 KB)
// ================================================================
static constexpr int FQS = 72;    // Q/K row stride (bf16 units)
static constexpr int FVU = 72;    // V/P row stride in 16-bit units (144B)
static constexpr int FLASH_SMEM = (128 * FQS * 3) * 2 + (2 * 256 * FVU) * 2 + (8 * 16 * FVU) * 2;

__global__ __launch_bounds__(256, 1)
void flash_attn_k(const bf16* __restrict__ Qg, const bf16* __restrict__ Kg,
                  const uint16_t* __restrict__ V8, uint16_t* __restrict__ O8) {
    extern __shared__ __align__(16) char fsm[];
    bf16* Qs = (bf16*)fsm;             // 128*72
    bf16* Ks = Qs + 128 * FQS;         // 2 bufs of 128*72
    bf16* Vs = Ks + 2 * 128 * FQS;     // 2 bufs of 256*72 units (fp8 pairs)
    bf16* Ps = Vs + 2 * 256 * FVU;     // 8 warps x 16*72 units

    int tid  = threadIdx.x;
    int warp = tid >> 5, lane = tid & 31;
    int rq = lane >> 2, cq = lane & 3;
    int l16 = lane & 15, lhi = (lane >> 4) * 8;
    int w16 = warp * 16;
    int qt = blockIdx.x & 7, dch = blockIdx.x >> 3;   // dch 0..1
    int b  = blockIdx.y >> 3, h = blockIdx.y & 7;

    const bf16* Qp = Qg + ((size_t)(b * 1024 + qt * 128)) * 512 + h * 64;
    const bf16* Kp = Kg + ((size_t)(b * 1024)) * 512 + h * 64;
    const uint16_t* Vp = V8 + (size_t)b * 2097152 + ((size_t)(h * 512 + dch * 256)) * 512;

#pragma unroll
    for (int p = 0; p < 4; p++) {
        int idx = tid + p * 256; int r = idx >> 3, c = (idx & 7) * 8;
        cpasync16(Qs + r * FQS + c, Qp + (size_t)r * 512 + c);
    }
    cpcommit();
#pragma unroll
    for (int p = 0; p < 4; p++) {
        int idx = tid + p * 256; int r = idx >> 3, c = (idx & 7) * 8;
        cpasync16(Ks + r * FQS + c, Kp + (size_t)r * 512 + c);
    }
#pragma unroll
    for (int p = 0; p < 8; p++) {
        int idx = tid + p * 256; int r = idx >> 3, c = (idx & 7) * 8;
        cpasync16(Vs + r * FVU + c, Vp + (size_t)r * 512 + c);
    }
    cpcommit();

    cpwait1();
    __syncthreads();
    uint32_t qfr[4][4];
#pragma unroll
    for (int kg = 0; kg < 4; kg++)
        ldsm_x4(qfr[kg][0], qfr[kg][1], qfr[kg][2], qfr[kg][3],
                Qs + (w16 + l16) * FQS + kg * 16 + lhi);

    float oacc[32][4];
#pragma unroll
    for (int n = 0; n < 32; n++)
#pragma unroll
        for (int r = 0; r < 4; r++) oacc[n][r] = 0.f;
    float m0 = -1e30f, m1 = -1e30f, l0 = 0.f, l1 = 0.f;

    uint16_t* Pw = (uint16_t*)Ps + warp * 16 * FVU;

    int cur = 0;
    for (int st = 0; st < 8; st++) {
        cpwait0();
        __syncthreads();
        if (st < 7) {
            int nb = cur ^ 1;
            int s1u = (st + 1) * 64;   // unit offset (128 fp8 per s-iter)
#pragma unroll
            for (int p = 0; p < 4; p++) {
                int idx = tid + p * 256; int r = idx >> 3, c = (idx & 7) * 8;
                cpasync16(Ks + nb * 128 * FQS + r * FQS + c,
                          Kp + (size_t)((st + 1) * 128 + r) * 512 + c);
            }
#pragma unroll
            for (int p = 0; p < 8; p++) {
                int idx = tid + p * 256; int r = idx >> 3, c = (idx & 7) * 8;
                cpasync16(Vs + nb * 256 * FVU + r * FVU + c, Vp + (size_t)r * 512 + s1u + c);
            }
            cpcommit();
        }

        // ---- S = Q·K^T : M=16 (warp rows), N=128, K=64 (bf16) ----
        float sacc[16][4];
#pragma unroll
        for (int j = 0; j < 16; j++)
#pragma unroll
            for (int r = 0; r < 4; r++) sacc[j][r] = 0.f;

        const bf16* Kc = Ks + cur * 128 * FQS;
#pragma unroll
        for (int kg = 0; kg < 4; kg++) {
#pragma unroll
            for (int jp = 0; jp < 8; jp++) {
                uint32_t b0, b1, b2, b3;
                ldsm_x4(b0, b1, b2, b3, Kc + (jp * 16 + l16) * FQS + kg * 16 + lhi);
                uint32_t bfA[2] = {b0, b2}, bfB[2] = {b1, b3};
                mma16816(sacc[2 * jp],     qfr[kg], bfA);
                mma16816(sacc[2 * jp + 1], qfr[kg], bfB);
            }
        }

        // mask (raw==0) + scale 1/8
#pragma unroll
        for (int j = 0; j < 16; j++)
#pragma unroll
            for (int r = 0; r < 4; r++) {
                float v = sacc[j][r];
                sacc[j][r] = (v == 0.f) ? -1e9f : v * 0.125f;
            }

        // ---- row max (quad shuffle only) ----
        float mx0 = -1e30f, mx1 = -1e30f;
#pragma unroll
        for (int j = 0; j < 16; j++) {
            mx0 = fmaxf(mx0, fmaxf(sacc[j][0], sacc[j][1]));
            mx1 = fmaxf(mx1, fmaxf(sacc[j][2], sacc[j][3]));
        }
        mx0 = fmaxf(mx0, __shfl_xor_sync(0xffffffffu, mx0, 1));
        mx0 = fmaxf(mx0, __shfl_xor_sync(0xffffffffu, mx0, 2));
        mx1 = fmaxf(mx1, __shfl_xor_sync(0xffffffffu, mx1, 1));
        mx1 = fmaxf(mx1, __shfl_xor_sync(0xffffffffu, mx1, 2));

        float nm0 = fmaxf(m0, mx0), nm1 = fmaxf(m1, mx1);
        float scf0 = __expf(m0 - nm0), scf1 = __expf(m1 - nm1);
        m0 = nm0; m1 = nm1;

#pragma unroll
        for (int n = 0; n < 32; n++) {
            oacc[n][0] *= scf0; oacc[n][1] *= scf0;
            oacc[n][2] *= scf1; oacc[n][3] *= scf1;
        }

        // ---- P = exp(S-m): fp8 x256 into per-warp smem tile + rowsum ----
        __syncwarp();
        float rs0 = 0.f, rs1 = 0.f;
#pragma unroll
        for (int j = 0; j < 16; j++) {
            float e0 = __expf(sacc[j][0] - m0), e1 = __expf(sacc[j][1] - m0);
            float e2 = __expf(sacc[j][2] - m1), e3 = __expf(sacc[j][3] - m1);
            rs0 += e0 + e1;
            rs1 += e2 + e3;
            Pw[rq * FVU + 4 * j + cq]       = pack_e4m3(SC_P * e0, SC_P * e1);
            Pw[(rq + 8) * FVU + 4 * j + cq] = pack_e4m3(SC_P * e2, SC_P * e3);
        }
        __syncwarp();
        rs0 += __shfl_xor_sync(0xffffffffu, rs0, 1);
        rs0 += __shfl_xor_sync(0xffffffffu, rs0, 2);
        rs1 += __shfl_xor_sync(0xffffffffu, rs1, 1);
        rs1 += __shfl_xor_sync(0xffffffffu, rs1, 2);
        l0 = l0 * scf0 + rs0;
        l1 = l1 * scf1 + rs1;

        // ---- O += P·V (fp8 m16n8k32): M=16, N=256 (d), K=128 (s) ----
        const bf16* Vc = Vs + cur * 256 * FVU;
#pragma unroll
        for (int kg = 0; kg < 4; kg++) {
            uint32_t af[4];
            ldsm_x4(af[0], af[1], af[2], af[3],
                    (bf16*)Pw + l16 * FVU + kg * 16 + lhi);
#pragma unroll
            for (int np = 0; np < 16; np++) {
                uint32_t b0, b1, b2, b3;
                ldsm_x4(b0, b1, b2, b3, Vc + (np * 16 + l16) * FVU + kg * 16 + lhi);
                uint32_t bfA[2] = {b0, b2}, bfB[2] = {b1, b3};
                mma16832(oacc[2 * np],     af, bfA);
                mma16832(oacc[2 * np + 1], af, bfB);
            }
        }
        cur ^= 1;
    }

    // ---- epilogue: (O / (SC_P * l)) * SC_O -> fp8 pairs ----
    float inv0 = (SC_O / SC_P) / l0, inv1 = (SC_O / SC_P) / l1;
    int row = b * 1024 + qt * 128 + w16 + rq;
    int colu = (h * 512 + dch * 256) / 2 + cq;   // unit index
#pragma unroll
    for (int n = 0; n < 32; n++) {
        int u = colu + n * 4;
        O8[(size_t)row * 2048 + u]       = pack_e4m3(oacc[n][0] * inv0, oacc[n][1] * inv0);
        O8[(size_t)(row + 8) * 2048 + u] = pack_e4m3(oacc[n][2] * inv1, oacc[n][3] * inv1);
    }
}

// -------- LayerNorm over D=512, eps=1e-6 --------
__global__ void layernorm_k(const float* __restrict__ y, const float* __restrict__ gamma,
                            const float* __restrict__ beta, float* __restrict__ out) {
    int row = blockIdx.x;
    int t = threadIdx.x;
    const float4* p = reinterpret_cast<const float4*>(y + (size_t)row * 512);
    float4 v = p[t];
    float s = v.x + v.y + v.z + v.w;
#pragma unroll
    for (int o = 16; o; o >>= 1) s += __shfl_xor_sync(0xffffffffu, s, o);
    __shared__ float sm[4];
    if ((t & 31) == 0) sm[t >> 5] = s;
    __syncthreads();
    float mu = (sm[0] + sm[1] + sm[2] + sm[3]) * (1.0f / 512.0f);
    float dx = v.x - mu, dy = v.y - mu, dz = v.z - mu, dw = v.w - mu;
    float q = dx * dx + dy * dy + dz * dz + dw * dw;
#pragma unroll
    for (int o = 16; o; o >>= 1) q += __shfl_xor_sync(0xffffffffu, q, o);
    __shared__ float sq[4];
    if ((t & 31) == 0) sq[t >> 5] = q;
    __syncthreads();
    float var = (sq[0] + sq[1] + sq[2] + sq[3]) * (1.0f / 512.0f);
    float rs = rsqrtf(var + 1e-6f);
    float4 g = reinterpret_cast<const float4*>(gamma)[t];
    float4 b = reinterpret_cast<const float4*>(beta)[t];
    float4 r;
    r.x = dx * rs * g.x + b.x;
    r.y = dy * rs * g.y + b.y;
    r.z = dz * rs * g.z + b.z;
    r.w = dw * rs * g.w + b.w;
    reinterpret_cast<float4*>(out + (size_t)row * 512)[t] = r;
}

// ---------------------------------------------------------------
extern "C" void kernel_launch(void* const* d_in, const int* in_sizes, int n_in,
                              void* d_out, int out_size) {
    const float* x     = (const float*)d_in[0];
    const float* Wq    = (const float*)d_in[1];
    const float* Wk    = (const float*)d_in[2];
    const float* Wv    = (const float*)d_in[3];
    const float* Wo    = (const float*)d_in[4];
    const float* bo    = (const float*)d_in[5];
    const float* gamma = (const float*)d_in[6];
    const float* beta  = (const float*)d_in[7];
    float* out = (float*)d_out;

    bf16 *xb, *qb, *kb, *wqt, *wkt, *wvt;
    uint16_t *wot8, *vt8, *ob8;
    float *yb;
    cudaGetSymbolAddress((void**)&xb,   g_xb);
    cudaGetSymbolAddress((void**)&qb,   g_qb);
    cudaGetSymbolAddress((void**)&kb,   g_kb);
    cudaGetSymbolAddress((void**)&wqt,  g_wqt);
    cudaGetSymbolAddress((void**)&wkt,  g_wkt);
    cudaGetSymbolAddress((void**)&wvt,  g_wvt);
    cudaGetSymbolAddress((void**)&wot8, g_wot8);
    cudaGetSymbolAddress((void**)&vt8,  g_vt8);
    cudaGetSymbolAddress((void**)&ob8,  g_ob8);
    cudaGetSymbolAddress((void**)&yb,   g_y);

    cudaFuncSetAttribute(flash_attn_k, cudaFuncAttributeMaxDynamicSharedMemorySize, FLASH_SMEM);

    // 1) x -> bf16
    f32_to_bf16_k<<<(int)(SZ_X / 4 / 256), 256>>>(x, xb, (int)SZ_X);
    // 2) transposed weights: Wq/Wk/Wv bf16, Wo fp8 (x64)
    transpose_to_bf16<<<dim3(16, 16),  dim3(32, 8)>>>(Wq, wqt, 512, 512);
    transpose_to_bf16<<<dim3(16, 16),  dim3(32, 8)>>>(Wk, wkt, 512, 512);
    transpose_to_bf16<<<dim3(128, 16), dim3(32, 8)>>>(Wv, wvt, 512, 4096);
    transpose_to_fp8 <<<dim3(16, 128), dim3(32, 8)>>>(Wo, wot8, 4096, 512, SC_WO);

    // 3) q = x @ Wq   [8192,512]  (bf16)
    gemm_tn<1, 0><<<dim3(4, 64, 1), 256>>>(xb, wqt, qb, 8192, 512, 512,
        512, 512, 512, 0, 0, 0, 0, 0, 0, 1, 1.0f, nullptr, nullptr, 0);
    // 4) k = x @ Wk   (bf16)
    gemm_tn<1, 0><<<dim3(4, 64, 1), 256>>>(xb, wkt, kb, 8192, 512, 512,
        512, 512, 512, 0, 0, 0, 0, 0, 0, 1, 1.0f, nullptr, nullptr, 0);
    // 5) Vt[b] = WvT @ x[b]^T -> fp8 [b][4096][512u]
    gemm_tn<3, 0><<<dim3(8, 32, 8), 256>>>(wvt, xb, vt8, 4096, 1024, 512,
        512, 512, 512, 0, 0, 0, 524288LL, 0, 2097152LL, 1, 1.0f, nullptr, nullptr, 0);
    // 6) fused attention (bf16 scores, fp8 P·V) -> ob8 (fp8 x32)
    flash_attn_k<<<dim3(16, 64), 256, FLASH_SMEM>>>(qb, kb, vt8, ob8);
    // 7) y = o @ Wo + bo + x   (fp8 GEMM, alpha = 1/(SC_O*SC_WO))
    gemm_tn<2, 1><<<dim3(4, 64, 1), 256>>>((const bf16*)ob8, (const bf16*)wot8, yb,
        8192, 512, 2048, 2048, 2048, 512, 0, 0, 0, 0, 0, 0, 1,
        1.0f / (SC_O * SC_WO), bo, x, 512);
    // 8) LayerNorm -> out
    layernorm_k<<<8192, 128>>>(yb, gamma, beta, out);
}

// round 11
// speedup vs baseline: 1.0218x; 1.0218x over previous
#include <cuda_runtime.h>
#include <cuda_bf16.h>
#include <cstdint>

using bf16 = __nv_bfloat16;

// Problem dims
static constexpr int NB = 8, NS = 1024, ND = 512, NK = 64, NH = 8;

static constexpr size_t SZ_X  = (size_t)NB * NS * ND;          // 4,194,304
static constexpr size_t SZ_VT = (size_t)NB * (ND * NH) * NS;   // 33,554,432
static constexpr size_t SZ_O  = (size_t)NB * NS * (NH * ND);   // 33,554,432

// -------- static scratch (no runtime allocation allowed) --------
__device__ bf16  g_xb  [SZ_X];
__device__ bf16  g_qkb [SZ_X * 2];        // [8192][1024]: q cols 0-511, k cols 512-1023
__device__ bf16  g_wqkt[1024 * ND];       // [1024][512]  rows 0-511 WqT, 512-1023 WkT
__device__ bf16  g_wvt[(ND * NH) * ND];   // [4096][512] WvT
__device__ bf16  g_wot[ND * (ND * NH)];   // [512][4096] WoT
__device__ bf16  g_vt [SZ_VT];            // [b][4096][1024]  V^T per batch
__device__ bf16  g_ob [SZ_O];             // [8192][4096] attention output
__device__ float g_y  [SZ_X];             // pre-LN (o@Wo + bo + x)

// ---------------------------------------------------------------
__device__ __forceinline__ uint32_t pack_bf16(float lo, float hi) {
    return ((uint32_t)__bfloat16_as_ushort(__float2bfloat16(hi)) << 16) |
            (uint32_t)__bfloat16_as_ushort(__float2bfloat16(lo));
}

__device__ __forceinline__ float ex2f(float x) {
    float r;
    asm("ex2.approx.f32 %0, %1;" : "=f"(r) : "f"(x));
    return r;
}

__device__ __forceinline__ void mma16816(float* d, const uint32_t* a, const uint32_t* b) {
    asm volatile(
        "mma.sync.aligned.m16n8k16.row.col.f32.bf16.bf16.f32 "
        "{%0,%1,%2,%3}, {%4,%5,%6,%7}, {%8,%9}, {%0,%1,%2,%3};\n"
        : "+f"(d[0]), "+f"(d[1]), "+f"(d[2]), "+f"(d[3])
        : "r"(a[0]), "r"(a[1]), "r"(a[2]), "r"(a[3]), "r"(b[0]), "r"(b[1]));
}

// ldmatrix x4: loads 4 8x8 bf16 matrices; per-lane row address in shared.
__device__ __forceinline__ void ldsm_x4(uint32_t& r0, uint32_t& r1, uint32_t& r2, uint32_t& r3,
                                        const void* p) {
    uint32_t a = (uint32_t)__cvta_generic_to_shared(p);
    asm volatile("ldmatrix.sync.aligned.m8n8.x4.shared.b16 {%0,%1,%2,%3}, [%4];"
                 : "=r"(r0), "=r"(r1), "=r"(r2), "=r"(r3) : "r"(a));
}

__device__ __forceinline__ void cpasync16(void* s, const void* g) {
    uint32_t sa = (uint32_t)__cvta_generic_to_shared(s);
    asm volatile("cp.async.cg.shared.global [%0], [%1], 16;\n" :: "r"(sa), "l"(g));
}
__device__ __forceinline__ void cpcommit() { asm volatile("cp.async.commit_group;\n" ::: "memory"); }
__device__ __forceinline__ void cpwait0()  { asm volatile("cp.async.wait_group 0;\n" ::: "memory"); }
__device__ __forceinline__ void cpwait1()  { asm volatile("cp.async.wait_group 1;\n" ::: "memory"); }

// -------- elementwise convert fp32 -> bf16 --------
__global__ void f32_to_bf16_k(const float* __restrict__ in, bf16* __restrict__ out, int n) {
    int i = (blockIdx.x * blockDim.x + threadIdx.x) * 4;
    if (i >= n) return;
    float4 v = *reinterpret_cast<const float4*>(in + i);
    uint2 u;
    u.x = pack_bf16(v.x, v.y);
    u.y = pack_bf16(v.z, v.w);
    *reinterpret_cast<uint2*>(out + i) = u;
}

// -------- transpose + convert: out[c][r] = in[r][c] --------
__global__ void transpose_to_bf16(const float* __restrict__ in, bf16* __restrict__ out,
                                  int R, int C) {
    __shared__ float t[32][33];
    int c0 = blockIdx.x * 32, r0 = blockIdx.y * 32;
    int tx = threadIdx.x;
    for (int i = threadIdx.y; i < 32; i += 8)
        t[i][tx] = in[(size_t)(r0 + i) * C + c0 + tx];
    __syncthreads();
    for (int i = threadIdx.y; i < 32; i += 8)
        out[(size_t)(c0 + i) * R + r0 + tx] = __float2bfloat16(t[tx][i]);
}

// -------- generic batched bf16 GEMM (cp.async double-buffered, ldmatrix frags) --------
// C[m,n] = alpha * sum_k A[m,k] * B[n,k]
// MODE 1: bf16 store     MODE 2: fp32 store + bias[n] + resid[m,n]
#define BM 128
#define BN 128
#define BK 32
#define BKP 40   // padded smem row (bf16); 80B row stride -> ldmatrix conflict-free

template <int MODE>
__global__ __launch_bounds__(256, 2)
void gemm_bf16_tn(const bf16* __restrict__ A, const bf16* __restrict__ B,
                  void* __restrict__ Cv,
                  int M, int N, int Kd, int lda, int ldb, int ldc,
                  long long sA1, long long sA2, long long sB1, long long sB2,
                  long long sC1, long long sC2, int Z1,
                  float alpha, const float* __restrict__ bias,
                  const float* __restrict__ resid, int ldres) {
    int z = blockIdx.z;
    int z1 = z % Z1, z2 = z / Z1;
    A += (size_t)z1 * sA1 + (size_t)z2 * sA2;
    B += (size_t)z1 * sB1 + (size_t)z2 * sB2;
    long long coff = (long long)z1 * sC1 + (long long)z2 * sC2;

    __shared__ alignas(16) bf16 As[2][BM][BKP];
    __shared__ alignas(16) bf16 Bs[2][BN][BKP];

    int tid  = threadIdx.x;
    int warp = tid >> 5, lane = tid & 31;
    int wm = (warp & 1) * 64;
    int wn = (warp >> 1) * 32;
    int bm0 = blockIdx.y * BM;
    int bn0 = blockIdx.x * BN;

    float acc[4][4][4];
#pragma unroll
    for (int i = 0; i < 4; i++)
#pragma unroll
        for (int j = 0; j < 4; j++)
#pragma unroll
            for (int r = 0; r < 4; r++) acc[i][j][r] = 0.f;

    int lr = tid >> 2;
    int lc = (tid & 3) * 8;
    int rq = lane >> 2;
    int cq = lane & 3;
    int l16 = lane & 15, lhi = (lane >> 4) * 8;

#pragma unroll
    for (int i = 0; i < 2; i++) {
        int r = lr + i * 64;
        cpasync16(&As[0][r][lc], A + (size_t)(bm0 + r) * lda + lc);
        cpasync16(&Bs[0][r][lc], B + (size_t)(bn0 + r) * ldb + lc);
    }
    cpcommit();

    int p = 0;
    for (int kt = 0; kt < Kd; kt += BK, p ^= 1) {
        cpwait0();
        __syncthreads();
        if (kt + BK < Kd) {
            int np = p ^ 1;
#pragma unroll
            for (int i = 0; i < 2; i++) {
                int r = lr + i * 64;
                cpasync16(&As[np][r][lc], A + (size_t)(bm0 + r) * lda + kt + BK + lc);
                cpasync16(&Bs[np][r][lc], B + (size_t)(bn0 + r) * ldb + kt + BK + lc);
            }
            cpcommit();
        }

#pragma unroll
        for (int ks = 0; ks < 2; ks++) {
            int kk = ks * 16 + lhi;
            uint32_t afr[4][4];
#pragma unroll
            for (int i = 0; i < 4; i++)
                ldsm_x4(afr[i][0], afr[i][1], afr[i][2], afr[i][3],
                        &As[p][wm + i * 16 + l16][kk]);
            uint32_t bfr[4][2];
#pragma unroll
            for (int jp = 0; jp < 2; jp++) {
                uint32_t b0, b1, b2, b3;
                ldsm_x4(b0, b1, b2, b3, &Bs[p][wn + jp * 16 + l16][kk]);
                bfr[2 * jp][0] = b0; bfr[2 * jp][1] = b2;
                bfr[2 * jp + 1][0] = b1; bfr[2 * jp + 1][1] = b3;
            }
#pragma unroll
            for (int i = 0; i < 4; i++)
#pragma unroll
                for (int j = 0; j < 4; j++)
                    mma16816(acc[i][j], afr[i], bfr[j]);
        }
        __syncthreads();
    }

    int cq2 = cq * 2;
    float* Cf = (MODE == 1) ? nullptr : (float*)Cv + coff;
    bf16*  Cb = (MODE == 1) ? (bf16*)Cv + coff : nullptr;
#pragma unroll
    for (int i = 0; i < 4; i++) {
#pragma unroll
        for (int j = 0; j < 4; j++) {
            int row = bm0 + wm + i * 16 + rq;
            int col = bn0 + wn + j * 8 + cq2;
            float c0 = acc[i][j][0] * alpha, c1 = acc[i][j][1] * alpha;
            float c2 = acc[i][j][2] * alpha, c3 = acc[i][j][3] * alpha;
            if (MODE == 2) {
                float b0v = bias[col], b1v = bias[col + 1];
                const float* r0p = resid + (size_t)row * ldres + col;
                const float* r1p = resid + (size_t)(row + 8) * ldres + col;
                c0 += b0v + r0p[0]; c1 += b1v + r0p[1];
                c2 += b0v + r1p[0]; c3 += b1v + r1p[1];
            }
            if (MODE == 1) {
                *reinterpret_cast<uint32_t*>(Cb + (size_t)row * ldc + col)       = pack_bf16(c0, c1);
                *reinterpret_cast<uint32_t*>(Cb + (size_t)(row + 8) * ldc + col) = pack_bf16(c2, c3);
            } else {
                *reinterpret_cast<float2*>(Cf + (size_t)row * ldc + col)       = make_float2(c0, c1);
                *reinterpret_cast<float2*>(Cf + (size_t)(row + 8) * ldc + col) = make_float2(c2, c3);
            }
        }
    }
}

// ================================================================
// Fused flash attention, FA2-style warp layout + ldmatrix fragment
// loads. d-chunk = 256; exp2-domain softmax (0.125*log2e folded into
// the mask/scale constant). Q/K read from merged qk buffer (stride
// 1024: q cols 0-511, k cols 512-1023).
// Block: q-tile 128 x d-chunk 256 for one (b,h); 8 s-iters of 128.
// grid = (16, 64): x = dch*8 + qt (dch 0..1), y = b*8 + h.
// Smem: Q[128*72] | K[2][128*72] | V[2][256*136]   (~190 KB)
// ================================================================
#define SCALE_LOG2 0.18033688f   // 0.125 * log2(e)
static constexpr int FQS = 72;    // Q/K row stride bf16 (144B, conflict-free)
static constexpr int FVS = 136;   // V row stride bf16 (272B, conflict-free)
static constexpr int FLASH_SMEM = (128 * FQS * 3 + 2 * 256 * FVS) * 2;

__global__ __launch_bounds__(256, 1)
void flash_attn_k(const bf16* __restrict__ QKg, const bf16* __restrict__ Vg,
                  bf16* __restrict__ Og) {
    extern __shared__ __align__(16) char fsm[];
    bf16* Qs = (bf16*)fsm;           // 128*72
    bf16* Ks = Qs + 128 * FQS;       // 2 bufs of 128*72
    bf16* Vs = Ks + 2 * 128 * FQS;   // 2 bufs of 256*136

    int tid  = threadIdx.x;
    int warp = tid >> 5, lane = tid & 31;
    int rq = lane >> 2, cq = lane & 3, cq2 = cq << 1;
    int l16 = lane & 15, lhi = (lane >> 4) * 8;
    int w16 = warp * 16;
    int qt = blockIdx.x & 7, dch = blockIdx.x >> 3;   // dch 0..1
    int b  = blockIdx.y >> 3, h = blockIdx.y & 7;

    const bf16* Qp = QKg + ((size_t)(b * 1024 + qt * 128)) * 1024 + h * 64;
    const bf16* Kp = QKg + ((size_t)(b * 1024)) * 1024 + 512 + h * 64;
    const bf16* Vp = Vg + (size_t)b * 4194304 + ((size_t)(h * 512 + dch * 256)) * 1024;

#pragma unroll
    for (int p = 0; p < 4; p++) {
        int idx = tid + p * 256; int r = idx >> 3, c = (idx & 7) * 8;
        cpasync16(Qs + r * FQS + c, Qp + (size_t)r * 1024 + c);
    }
    cpcommit();
#pragma unroll
    for (int p = 0; p < 4; p++) {
        int idx = tid + p * 256; int r = idx >> 3, c = (idx & 7) * 8;
        cpasync16(Ks + r * FQS + c, Kp + (size_t)r * 1024 + c);
    }
#pragma unroll
    for (int p = 0; p < 16; p++) {
        int idx = tid + p * 256; int r = idx >> 4, c = (idx & 15) * 8;
        cpasync16(Vs + r * FVS + c, Vp + (size_t)r * 1024 + c);
    }
    cpcommit();

    cpwait1();
    __syncthreads();
    uint32_t qfr[4][4];
#pragma unroll
    for (int kg = 0; kg < 4; kg++)
        ldsm_x4(qfr[kg][0], qfr[kg][1], qfr[kg][2], qfr[kg][3],
                Qs + (w16 + l16) * FQS + kg * 16 + lhi);

    float oacc[32][4];
#pragma unroll
    for (int n = 0; n < 32; n++)
#pragma unroll
        for (int r = 0; r < 4; r++) oacc[n][r] = 0.f;
    float m0 = -1e30f, m1 = -1e30f, l0 = 0.f, l1 = 0.f;

    int cur = 0;
    for (int st = 0; st < 8; st++) {
        cpwait0();
        __syncthreads();
        if (st < 7) {
            int nb = cur ^ 1;
            int s1 = (st + 1) * 128;
#pragma unroll
            for (int p = 0; p < 4; p++) {
                int idx = tid + p * 256; int r = idx >> 3, c = (idx & 7) * 8;
                cpasync16(Ks + nb * 128 * FQS + r * FQS + c, Kp + (size_t)(s1 + r) * 1024 + c);
            }
#pragma unroll
            for (int p = 0; p < 16; p++) {
                int idx = tid + p * 256; int r = idx >> 4, c = (idx & 15) * 8;
                cpasync16(Vs + nb * 256 * FVS + r * FVS + c, Vp + (size_t)r * 1024 + s1 + c);
            }
            cpcommit();
        }

        // ---- S = Q·K^T : M=16 (warp rows), N=128, K=64 ----
        float sacc[16][4];
#pragma unroll
        for (int j = 0; j < 16; j++)
#pragma unroll
            for (int r = 0; r < 4; r++) sacc[j][r] = 0.f;

        const bf16* Kc = Ks + cur * 128 * FQS;
#pragma unroll
        for (int kg = 0; kg < 4; kg++) {
#pragma unroll
            for (int jp = 0; jp < 8; jp++) {
                uint32_t b0, b1, b2, b3;
                ldsm_x4(b0, b1, b2, b3, Kc + (jp * 16 + l16) * FQS + kg * 16 + lhi);
                uint32_t bfA[2] = {b0, b2}, bfB[2] = {b1, b3};
                mma16816(sacc[2 * jp],     qfr[kg], bfA);
                mma16816(sacc[2 * jp + 1], qfr[kg], bfB);
            }
        }

        // mask (raw==0) + scale into log2 domain (0.125*log2e)
#pragma unroll
        for (int j = 0; j < 16; j++)
#pragma unroll
            for (int r = 0; r < 4; r++) {
                float v = sacc[j][r];
                sacc[j][r] = (v == 0.f) ? -1e9f : v * SCALE_LOG2;
            }

        // ---- row max (quad shuffle only) ----
        float mx0 = -1e30f, mx1 = -1e30f;
#pragma unroll
        for (int j = 0; j < 16; j++) {
            mx0 = fmaxf(mx0, fmaxf(sacc[j][0], sacc[j][1]));
            mx1 = fmaxf(mx1, fmaxf(sacc[j][2], sacc[j][3]));
        }
        mx0 = fmaxf(mx0, __shfl_xor_sync(0xffffffffu, mx0, 1));
        mx0 = fmaxf(mx0, __shfl_xor_sync(0xffffffffu, mx0, 2));
        mx1 = fmaxf(mx1, __shfl_xor_sync(0xffffffffu, mx1, 1));
        mx1 = fmaxf(mx1, __shfl_xor_sync(0xffffffffu, mx1, 2));

        float nm0 = fmaxf(m0, mx0), nm1 = fmaxf(m1, mx1);
        float scf0 = ex2f(m0 - nm0), scf1 = ex2f(m1 - nm1);
        m0 = nm0; m1 = nm1;

#pragma unroll
        for (int n = 0; n < 32; n++) {
            oacc[n][0] *= scf0; oacc[n][1] *= scf0;
            oacc[n][2] *= scf1; oacc[n][3] *= scf1;
        }

        // ---- P = exp2(S' - m') in registers + rowsum ----
        uint32_t pf[8][4];
        float rs0 = 0.f, rs1 = 0.f;
#pragma unroll
        for (int kg = 0; kg < 8; kg++) {
            int j0 = 2 * kg, j1 = 2 * kg + 1;
            float e00 = ex2f(sacc[j0][0] - m0), e01 = ex2f(sacc[j0][1] - m0);
            float e02 = ex2f(sacc[j0][2] - m1), e03 = ex2f(sacc[j0][3] - m1);
            float e10 = ex2f(sacc[j1][0] - m0), e11 = ex2f(sacc[j1][1] - m0);
            float e12 = ex2f(sacc[j1][2] - m1), e13 = ex2f(sacc[j1][3] - m1);
            rs0 += e00 + e01 + e10 + e11;
            rs1 += e02 + e03 + e12 + e13;
            pf[kg][0] = pack_bf16(e00, e01);
            pf[kg][1] = pack_bf16(e02, e03);
            pf[kg][2] = pack_bf16(e10, e11);
            pf[kg][3] = pack_bf16(e12, e13);
        }
        rs0 += __shfl_xor_sync(0xffffffffu, rs0, 1);
        rs0 += __shfl_xor_sync(0xffffffffu, rs0, 2);
        rs1 += __shfl_xor_sync(0xffffffffu, rs1, 1);
        rs1 += __shfl_xor_sync(0xffffffffu, rs1, 2);
        l0 = l0 * scf0 + rs0;
        l1 = l1 * scf1 + rs1;

        // ---- O += P·V : M=16, N=256 (d), K=128 (s) ----
        const bf16* Vc = Vs + cur * 256 * FVS;
#pragma unroll
        for (int kg = 0; kg < 8; kg++) {
#pragma unroll
            for (int np = 0; np < 16; np++) {
                uint32_t b0, b1, b2, b3;
                ldsm_x4(b0, b1, b2, b3, Vc + (np * 16 + l16) * FVS + kg * 16 + lhi);
                uint32_t bfA[2] = {b0, b2}, bfB[2] = {b1, b3};
                mma16816(oacc[2 * np],     pf[kg], bfA);
                mma16816(oacc[2 * np + 1], pf[kg], bfB);
            }
        }
        cur ^= 1;
    }

    // ---- epilogue: O / l -> ob (bf16) ----
    float inv0 = 1.f / l0, inv1 = 1.f / l1;
    int row = b * 1024 + qt * 128 + w16 + rq;
    int colb = h * 512 + dch * 256 + cq2;
#pragma unroll
    for (int n = 0; n < 32; n++) {
        int col = colb + n * 8;
        *reinterpret_cast<uint32_t*>(Og + (size_t)row * 4096 + col) =
            pack_bf16(oacc[n][0] * inv0, oacc[n][1] * inv0);
        *reinterpret_cast<uint32_t*>(Og + (size_t)(row + 8) * 4096 + col) =
            pack_bf16(oacc[n][2] * inv1, oacc[n][3] * inv1);
    }
}

// -------- LayerNorm over D=512, eps=1e-6 --------
__global__ void layernorm_k(const float* __restrict__ y, const float* __restrict__ gamma,
                            const float* __restrict__ beta, float* __restrict__ out) {
    int row = blockIdx.x;
    int t = threadIdx.x;
    const float4* p = reinterpret_cast<const float4*>(y + (size_t)row * 512);
    float4 v = p[t];
    float s = v.x + v.y + v.z + v.w;
#pragma unroll
    for (int o = 16; o; o >>= 1) s += __shfl_xor_sync(0xffffffffu, s, o);
    __shared__ float sm[4];
    if ((t & 31) == 0) sm[t >> 5] = s;
    __syncthreads();
    float mu = (sm[0] + sm[1] + sm[2] + sm[3]) * (1.0f / 512.0f);
    float dx = v.x - mu, dy = v.y - mu, dz = v.z - mu, dw = v.w - mu;
    float q = dx * dx + dy * dy + dz * dz + dw * dw;
#pragma unroll
    for (int o = 16; o; o >>= 1) q += __shfl_xor_sync(0xffffffffu, q, o);
    __shared__ float sq[4];
    if ((t & 31) == 0) sq[t >> 5] = q;
    __syncthreads();
    float var = (sq[0] + sq[1] + sq[2] + sq[3]) * (1.0f / 512.0f);
    float rs = rsqrtf(var + 1e-6f);
    float4 g = reinterpret_cast<const float4*>(gamma)[t];
    float4 b = reinterpret_cast<const float4*>(beta)[t];
    float4 r;
    r.x = dx * rs * g.x + b.x;
    r.y = dy * rs * g.y + b.y;
    r.z = dz * rs * g.z + b.z;
    r.w = dw * rs * g.w + b.w;
    reinterpret_cast<float4*>(out + (size_t)row * 512)[t] = r;
}

// ---------------------------------------------------------------
extern "C" void kernel_launch(void* const* d_in, const int* in_sizes, int n_in,
                              void* d_out, int out_size) {
    const float* x     = (const float*)d_in[0];
    const float* Wq    = (const float*)d_in[1];
    const float* Wk    = (const float*)d_in[2];
    const float* Wv    = (const float*)d_in[3];
    const float* Wo    = (const float*)d_in[4];
    const float* bo    = (const float*)d_in[5];
    const float* gamma = (const float*)d_in[6];
    const float* beta  = (const float*)d_in[7];
    float* out = (float*)d_out;

    bf16 *xb, *qkb, *wqkt, *wvt, *wot, *vt, *ob;
    float *yb;
    cudaGetSymbolAddress((void**)&xb,   g_xb);
    cudaGetSymbolAddress((void**)&qkb,  g_qkb);
    cudaGetSymbolAddress((void**)&wqkt, g_wqkt);
    cudaGetSymbolAddress((void**)&wvt,  g_wvt);
    cudaGetSymbolAddress((void**)&wot,  g_wot);
    cudaGetSymbolAddress((void**)&vt,   g_vt);
    cudaGetSymbolAddress((void**)&ob,   g_ob);
    cudaGetSymbolAddress((void**)&yb,   g_y);

    cudaFuncSetAttribute(flash_attn_k, cudaFuncAttributeMaxDynamicSharedMemorySize, FLASH_SMEM);

    // 1) x -> bf16
    f32_to_bf16_k<<<(int)(SZ_X / 4 / 256), 256>>>(x, xb, (int)SZ_X);
    // 2) transposed bf16 weights (Wq and Wk into one concatenated buffer)
    transpose_to_bf16<<<dim3(16, 16),  dim3(32, 8)>>>(Wq, wqkt, 512, 512);
    transpose_to_bf16<<<dim3(16, 16),  dim3(32, 8)>>>(Wk, wqkt + 512 * 512, 512, 512);
    transpose_to_bf16<<<dim3(128, 16), dim3(32, 8)>>>(Wv, wvt, 512, 4096);
    transpose_to_bf16<<<dim3(16, 128), dim3(32, 8)>>>(Wo, wot, 4096, 512);

    // 3) [q|k] = x @ [Wq|Wk]   [8192,1024]
    gemm_bf16_tn<1><<<dim3(8, 64, 1), 256>>>(xb, wqkt, qkb, 8192, 1024, 512,
        512, 512, 1024, 0, 0, 0, 0, 0, 0, 1, 1.0f, nullptr, nullptr, 0);
    // 4) Vt[b] = WvT @ x[b]^T  -> [b][4096][1024]
    gemm_bf16_tn<1><<<dim3(8, 32, 8), 256>>>(wvt, xb, vt, 4096, 1024, 512,
        512, 512, 1024, 0, 0, 0, 524288LL, 0, 4194304LL, 1, 1.0f, nullptr, nullptr, 0);
    // 5) fused attention: scores + mask + softmax + P·V -> ob  (d-chunk 256)
    flash_attn_k<<<dim3(16, 64), 256, FLASH_SMEM>>>(qkb, vt, ob);
    // 6) y = o @ Wo + bo + x
    gemm_bf16_tn<2><<<dim3(4, 64, 1), 256>>>(ob, wot, yb, 8192, 512, 4096,
        4096, 4096, 512, 0, 0, 0, 0, 0, 0, 1, 1.0f, bo, x, 512);
    // 7) LayerNorm -> out
    layernorm_k<<<8192, 128>>>(yb, gamma, beta, out);
}